// round 1
// baseline (speedup 1.0000x reference)
#include <cuda_runtime.h>
#include <math.h>

#define NN 16384
#define GG 128
#define E0C 262144
#define KK 8

// ---------------- scratch (device globals; no allocations allowed) ----------
__device__ float g_h1[NN * 16];
__device__ float g_h2[NN * 8];
__device__ float g_sq[NN];
__device__ int   g_knn[NN * KK];
__device__ float g_h3[NN * 8];
__device__ float g_h4[NN * 16];

// ---------------- init: zero atomic-max accumulators ------------------------
__global__ void k_init() {
    int i = blockIdx.x * blockDim.x + threadIdx.x;
    if (i < NN * 16) g_h1[i] = 0.0f;
    if (i < NN * 8)  g_h2[i] = 0.0f;
}

// ---------------- conv1: x[N,3] -> h1[N,16] (6->16 relu ->16) ---------------
__global__ void k_conv1(const float* __restrict__ x, const int* __restrict__ ei,
                        const float* __restrict__ w1, const float* __restrict__ b1,
                        const float* __restrict__ w2, const float* __restrict__ b2) {
    __shared__ float sw1[96], sb1[16], sw2[256], sb2[16];
    int t = threadIdx.x;
    for (int v = t; v < 96;  v += blockDim.x) sw1[v] = w1[v];
    for (int v = t; v < 256; v += blockDim.x) sw2[v] = w2[v];
    if (t < 16) { sb1[t] = b1[t]; sb2[t] = b2[t]; }
    __syncthreads();
    int e = blockIdx.x * blockDim.x + t;
    if (e >= E0C) return;
    int s = ei[e], d = ei[E0C + e];
    float xi0 = x[d * 3], xi1 = x[d * 3 + 1], xi2 = x[d * 3 + 2];
    float m[6] = { xi0, xi1, xi2,
                   x[s * 3] - xi0, x[s * 3 + 1] - xi1, x[s * 3 + 2] - xi2 };
    float h[16];
#pragma unroll
    for (int o = 0; o < 16; ++o) h[o] = sb1[o];
#pragma unroll
    for (int i = 0; i < 6; ++i) {
        float mv = m[i];
#pragma unroll
        for (int o = 0; o < 16; ++o) h[o] += mv * sw1[i * 16 + o];
    }
#pragma unroll
    for (int o = 0; o < 16; ++o) h[o] = fmaxf(h[o], 0.0f);
    int* dst = (int*)&g_h1[d * 16];
#pragma unroll
    for (int o = 0; o < 16; ++o) {
        float v = sb2[o];
#pragma unroll
        for (int i = 0; i < 16; ++i) v += h[i] * sw2[i * 16 + o];
        atomicMax(dst + o, __float_as_int(fmaxf(v, 0.0f)));
    }
}

// ---------------- conv2: h1[N,16] -> h2[N,8] (32->8 relu ->8) ---------------
__global__ void k_conv2(const int* __restrict__ ei,
                        const float* __restrict__ w1, const float* __restrict__ b1,
                        const float* __restrict__ w2, const float* __restrict__ b2) {
    __shared__ float sw1[256], sb1[8], sw2[64], sb2[8];
    int t = threadIdx.x;
    for (int v = t; v < 256; v += blockDim.x) sw1[v] = w1[v];
    for (int v = t; v < 64;  v += blockDim.x) sw2[v] = w2[v];
    if (t < 8) { sb1[t] = b1[t]; sb2[t] = b2[t]; }
    __syncthreads();
    int e = blockIdx.x * blockDim.x + t;
    if (e >= E0C) return;
    int s = ei[e], d = ei[E0C + e];
    const float4* Xi = (const float4*)&g_h1[d * 16];
    const float4* Xj = (const float4*)&g_h1[s * 16];
    float xi[16], xj[16];
#pragma unroll
    for (int q = 0; q < 4; ++q) {
        float4 a = Xi[q], b = Xj[q];
        xi[q * 4 + 0] = a.x; xi[q * 4 + 1] = a.y; xi[q * 4 + 2] = a.z; xi[q * 4 + 3] = a.w;
        xj[q * 4 + 0] = b.x; xj[q * 4 + 1] = b.y; xj[q * 4 + 2] = b.z; xj[q * 4 + 3] = b.w;
    }
    float h[8];
#pragma unroll
    for (int o = 0; o < 8; ++o) h[o] = sb1[o];
#pragma unroll
    for (int f = 0; f < 16; ++f) {
        float m0 = xi[f], m1 = xj[f] - xi[f];
#pragma unroll
        for (int o = 0; o < 8; ++o)
            h[o] += m0 * sw1[f * 8 + o] + m1 * sw1[(16 + f) * 8 + o];
    }
#pragma unroll
    for (int o = 0; o < 8; ++o) h[o] = fmaxf(h[o], 0.0f);
    int* dst = (int*)&g_h2[d * 8];
#pragma unroll
    for (int o = 0; o < 8; ++o) {
        float v = sb2[o];
#pragma unroll
        for (int i = 0; i < 8; ++i) v += h[i] * sw2[i * 8 + o];
        atomicMax(dst + o, __float_as_int(fmaxf(v, 0.0f)));
    }
}

// ---------------- squared norms ----------------------------------------------
__global__ void k_sq() {
    int i = blockIdx.x * blockDim.x + threadIdx.x;
    if (i >= NN) return;
    float4 a = ((const float4*)g_h2)[i * 2];
    float4 b = ((const float4*)g_h2)[i * 2 + 1];
    g_sq[i] = a.x * a.x + a.y * a.y + a.z * a.z + a.w * a.w +
              b.x * b.x + b.y * b.y + b.z * b.z + b.w * b.w;
}

// ---------------- kNN: global top-8 by squared distance ----------------------
// 4 threads per query, each scans 1/4 of each shared tile, local top-8 in regs,
// then a 4-way lexicographic merge ((d, idx) — matches lax.top_k tie behavior).
#define KTILE 512
__global__ void __launch_bounds__(128) k_knn() {
    __shared__ float4 sp[KTILE * 2];
    __shared__ float  ssq[KTILE];
    __shared__ float  md[128 * 8];
    __shared__ int    mi[128 * 8];
    int t = threadIdx.x;
    int gq = (blockIdx.x * 128 + t) >> 2;  // query node
    int slice = t & 3;
    float4 q0 = ((const float4*)g_h2)[gq * 2];
    float4 q1 = ((const float4*)g_h2)[gq * 2 + 1];
    float sqi = g_sq[gq];
    float best[8]; int bidx[8];
#pragma unroll
    for (int r = 0; r < 8; ++r) { best[r] = INFINITY; bidx[r] = -1; }

    for (int tb = 0; tb < NN; tb += KTILE) {
        __syncthreads();
        for (int v = t; v < KTILE * 2; v += 128)
            sp[v] = ((const float4*)g_h2)[tb * 2 + v];
        for (int v = t; v < KTILE; v += 128)
            ssq[v] = g_sq[tb + v];
        __syncthreads();
        int jbase = slice * (KTILE / 4);
#pragma unroll 4
        for (int jj = 0; jj < KTILE / 4; ++jj) {
            int jl = jbase + jj;
            float4 p0 = sp[jl * 2], p1 = sp[jl * 2 + 1];
            float dot = p0.x * q0.x + p0.y * q0.y + p0.z * q0.z + p0.w * q0.w +
                        p1.x * q1.x + p1.y * q1.y + p1.z * q1.z + p1.w * q1.w;
            float dd = sqi + ssq[jl] - 2.0f * dot;
            int jg = tb + jl;
            if (jg == gq) dd = INFINITY;
            if (dd < best[7]) {
                best[7] = dd; bidx[7] = jg;
#pragma unroll
                for (int r = 7; r > 0; --r) {
                    if (best[r] < best[r - 1]) {
                        float td = best[r]; best[r] = best[r - 1]; best[r - 1] = td;
                        int ti = bidx[r]; bidx[r] = bidx[r - 1]; bidx[r - 1] = ti;
                    }
                }
            }
        }
    }
    __syncthreads();
#pragma unroll
    for (int r = 0; r < 8; ++r) { md[t * 8 + r] = best[r]; mi[t * 8 + r] = bidx[r]; }
    __syncthreads();
    if (slice == 0) {
        int b0 = t * 8;  // this thread's 4 lists are contiguous: t, t+1, t+2, t+3
        int p0 = 0, p1 = 0, p2 = 0, p3 = 0;
#pragma unroll
        for (int r = 0; r < 8; ++r) {
            float d0 = md[b0 + p0],      d1 = md[b0 + 8 + p1];
            float d2 = md[b0 + 16 + p2], d3 = md[b0 + 24 + p3];
            int   i0 = mi[b0 + p0],      i1 = mi[b0 + 8 + p1];
            int   i2 = mi[b0 + 16 + p2], i3 = mi[b0 + 24 + p3];
            float bd = d0; int bi = i0; int bs = 0;
            if (d1 < bd || (d1 == bd && i1 < bi)) { bd = d1; bi = i1; bs = 1; }
            if (d2 < bd || (d2 == bd && i2 < bi)) { bd = d2; bi = i2; bs = 2; }
            if (d3 < bd || (d3 == bd && i3 < bi)) { bd = d3; bi = i3; bs = 3; }
            if      (bs == 0) ++p0;
            else if (bs == 1) ++p1;
            else if (bs == 2) ++p2;
            else              ++p3;
            g_knn[gq * 8 + r] = bi;
        }
    }
}

// ---------------- conv3: h2[N,8] -> h3[N,8] over kNN edges (16->8 relu ->8) --
__global__ void k_conv3(const float* __restrict__ w1, const float* __restrict__ b1,
                        const float* __restrict__ w2, const float* __restrict__ b2) {
    __shared__ float sw1[128], sb1[8], sw2[64], sb2[8];
    int t = threadIdx.x;
    for (int v = t; v < 128; v += blockDim.x) sw1[v] = w1[v];
    for (int v = t; v < 64;  v += blockDim.x) sw2[v] = w2[v];
    if (t < 8) { sb1[t] = b1[t]; sb2[t] = b2[t]; }
    __syncthreads();
    int i = blockIdx.x * blockDim.x + t;
    float xi[8];
    {
        float4 a = ((const float4*)g_h2)[i * 2];
        float4 b = ((const float4*)g_h2)[i * 2 + 1];
        xi[0] = a.x; xi[1] = a.y; xi[2] = a.z; xi[3] = a.w;
        xi[4] = b.x; xi[5] = b.y; xi[6] = b.z; xi[7] = b.w;
    }
    float out[8];
#pragma unroll
    for (int o = 0; o < 8; ++o) out[o] = 0.0f;
#pragma unroll
    for (int n = 0; n < 8; ++n) {
        int j = g_knn[i * 8 + n];
        float4 c = ((const float4*)g_h2)[j * 2];
        float4 d = ((const float4*)g_h2)[j * 2 + 1];
        float xj[8] = { c.x, c.y, c.z, c.w, d.x, d.y, d.z, d.w };
        float h[8];
#pragma unroll
        for (int o = 0; o < 8; ++o) h[o] = sb1[o];
#pragma unroll
        for (int f = 0; f < 8; ++f) {
            float m0 = xi[f], m1 = xj[f] - xi[f];
#pragma unroll
            for (int o = 0; o < 8; ++o)
                h[o] += m0 * sw1[f * 8 + o] + m1 * sw1[(8 + f) * 8 + o];
        }
#pragma unroll
        for (int o = 0; o < 8; ++o) h[o] = fmaxf(h[o], 0.0f);
#pragma unroll
        for (int o = 0; o < 8; ++o) {
            float v = sb2[o];
#pragma unroll
            for (int f = 0; f < 8; ++f) v += h[f] * sw2[f * 8 + o];
            out[o] = fmaxf(out[o], v);
        }
    }
#pragma unroll
    for (int o = 0; o < 8; ++o) g_h3[i * 8 + o] = out[o];
}

// ---------------- conv4: h3[N,8] -> h4[N,16] over kNN edges (16->16 relu ->16)
__global__ void k_conv4(const float* __restrict__ w1, const float* __restrict__ b1,
                        const float* __restrict__ w2, const float* __restrict__ b2) {
    __shared__ float sw1[256], sb1[16], sw2[256], sb2[16];
    int t = threadIdx.x;
    for (int v = t; v < 256; v += blockDim.x) { sw1[v] = w1[v]; sw2[v] = w2[v]; }
    if (t < 16) { sb1[t] = b1[t]; sb2[t] = b2[t]; }
    __syncthreads();
    int i = blockIdx.x * blockDim.x + t;
    float xi[8];
    {
        float4 a = ((const float4*)g_h3)[i * 2];
        float4 b = ((const float4*)g_h3)[i * 2 + 1];
        xi[0] = a.x; xi[1] = a.y; xi[2] = a.z; xi[3] = a.w;
        xi[4] = b.x; xi[5] = b.y; xi[6] = b.z; xi[7] = b.w;
    }
    float out[16];
#pragma unroll
    for (int o = 0; o < 16; ++o) out[o] = 0.0f;
#pragma unroll
    for (int n = 0; n < 8; ++n) {
        int j = g_knn[i * 8 + n];
        float4 c = ((const float4*)g_h3)[j * 2];
        float4 d = ((const float4*)g_h3)[j * 2 + 1];
        float xj[8] = { c.x, c.y, c.z, c.w, d.x, d.y, d.z, d.w };
        float h[16];
#pragma unroll
        for (int o = 0; o < 16; ++o) h[o] = sb1[o];
#pragma unroll
        for (int f = 0; f < 8; ++f) {
            float m0 = xi[f], m1 = xj[f] - xi[f];
#pragma unroll
            for (int o = 0; o < 16; ++o)
                h[o] += m0 * sw1[f * 16 + o] + m1 * sw1[(8 + f) * 16 + o];
        }
#pragma unroll
        for (int o = 0; o < 16; ++o) h[o] = fmaxf(h[o], 0.0f);
#pragma unroll
        for (int o = 0; o < 16; ++o) {
            float v = sb2[o];
#pragma unroll
            for (int f = 0; f < 16; ++f) v += h[f] * sw2[f * 16 + o];
            out[o] = fmaxf(out[o], v);
        }
    }
#pragma unroll
    for (int o = 0; o < 16; ++o) g_h4[i * 16 + o] = out[o];
}

// ---------------- global max pool + MLP head + sigmoid -----------------------
__global__ void k_pool(const float* __restrict__ fw, const float* __restrict__ fb,
                       const float* __restrict__ ow, const float* __restrict__ ob,
                       float* __restrict__ out) {
    __shared__ float s[128 * 16];
    int g = blockIdx.x, t = threadIdx.x;
    int node = g * 128 + t;
#pragma unroll
    for (int f = 0; f < 16; ++f) s[t * 16 + f] = g_h4[node * 16 + f];
    __syncthreads();
    for (int st = 64; st > 0; st >>= 1) {
        if (t < st) {
#pragma unroll
            for (int f = 0; f < 16; ++f)
                s[t * 16 + f] = fmaxf(s[t * 16 + f], s[(t + st) * 16 + f]);
        }
        __syncthreads();
    }
    if (t == 0) {
        float z = ob[0];
#pragma unroll
        for (int o = 0; o < 6; ++o) {
            float y = fb[o];
#pragma unroll
            for (int f = 0; f < 16; ++f) y += s[f] * fw[f * 6 + o];
            z += fmaxf(y, 0.0f) * ow[o];
        }
        out[g] = 1.0f / (1.0f + expf(-z));
    }
}

// ---------------- launch ------------------------------------------------------
extern "C" void kernel_launch(void* const* d_in, const int* in_sizes, int n_in,
                              void* d_out, int out_size) {
    const float* x    = (const float*)d_in[0];
    const int*   ei   = (const int*)d_in[1];
    const float* c1w1 = (const float*)d_in[3];
    const float* c1b1 = (const float*)d_in[4];
    const float* c1w2 = (const float*)d_in[5];
    const float* c1b2 = (const float*)d_in[6];
    const float* c2w1 = (const float*)d_in[7];
    const float* c2b1 = (const float*)d_in[8];
    const float* c2w2 = (const float*)d_in[9];
    const float* c2b2 = (const float*)d_in[10];
    const float* c3w1 = (const float*)d_in[11];
    const float* c3b1 = (const float*)d_in[12];
    const float* c3w2 = (const float*)d_in[13];
    const float* c3b2 = (const float*)d_in[14];
    const float* c4w1 = (const float*)d_in[15];
    const float* c4b1 = (const float*)d_in[16];
    const float* c4w2 = (const float*)d_in[17];
    const float* c4b2 = (const float*)d_in[18];
    const float* fc3w = (const float*)d_in[19];
    const float* fc3b = (const float*)d_in[20];
    const float* outw = (const float*)d_in[21];
    const float* outb = (const float*)d_in[22];

    k_init <<< (NN * 16 + 255) / 256, 256 >>> ();
    k_conv1<<< E0C / 256, 256 >>>(x, ei, c1w1, c1b1, c1w2, c1b2);
    k_conv2<<< E0C / 256, 256 >>>(ei, c2w1, c2b1, c2w2, c2b2);
    k_sq   <<< NN / 256, 256 >>>();
    k_knn  <<< NN / 32, 128 >>>();
    k_conv3<<< NN / 128, 128 >>>(c3w1, c3b1, c3w2, c3b2);
    k_conv4<<< NN / 128, 128 >>>(c4w1, c4b1, c4w2, c4b2);
    k_pool <<< GG, 128 >>>(fc3w, fc3b, outw, outb, (float*)d_out);
}